// round 8
// baseline (speedup 1.0000x reference)
#include <cuda_runtime.h>
#include <cstdint>

#define Bsz 4
#define Ssz 512
#define Dsz 768
#define Hn  12
#define DHn 64
#define SDn 30

// ---- scratch (static device globals; no runtime allocation) ----
__device__ float g_q  [Bsz*Hn*Ssz*DHn];          // (B,H,S,DH) scaled q
__device__ float g_k  [Bsz*Hn*Ssz*DHn];
__device__ float g_v  [Bsz*Hn*Ssz*DHn];
__device__ float g_ctx[Bsz*Ssz*Dsz];             // (B,S,H*DH)
__device__ float g_qs [Bsz*Hn*Ssz*SDn];          // q @ Wsk^T
__device__ float g_A  [Bsz*Hn*Ssz*SDn];          // attn . structure
__device__ float g_sc [(size_t)Bsz*Hn*Ssz*Ssz];  // scores / attn (in place)
__device__ int   g_maskmode;                     // 1 = byte mask, 0 = int32 mask

__global__ void detect_mask(const unsigned int* __restrict__ m, int n_words)
{
    __shared__ int found;
    if (threadIdx.x == 0) found = 0;
    __syncthreads();
    for (int i = threadIdx.x; i < n_words; i += blockDim.x) {
        if (m[i] > 1u) { found = 1; break; }
    }
    __syncthreads();
    if (threadIdx.x == 0) g_maskmode = found;
}

__device__ __forceinline__ uint32_t f2tf(float x)
{
    uint32_t u;
    asm("cvt.rna.tf32.f32 %0, %1;" : "=r"(u) : "f"(x));
    return u;
}

__device__ __forceinline__ void mma8(float& d0, float& d1, float& d2, float& d3,
                                     uint32_t a0, uint32_t a1, uint32_t a2, uint32_t a3,
                                     uint32_t b0, uint32_t b1)
{
    asm volatile("mma.sync.aligned.m16n8k8.row.col.f32.tf32.tf32.f32 "
                 "{%0,%1,%2,%3}, {%4,%5,%6,%7}, {%8,%9}, {%0,%1,%2,%3};\n"
                 : "+f"(d0), "+f"(d1), "+f"(d2), "+f"(d3)
                 : "r"(a0), "r"(a1), "r"(a2), "r"(a3), "r"(b0), "r"(b1));
}

// ---------------------------------------------------------------------------
// tf32 tensor-core GEMM: CTA tile 128x64, BK=16, 256 threads (8 warps, each
// computing 32x32 via m16n8k8 fragments), double-buffered smem.
// modes: 0 = fused QKV projections (z selects input/weight/bias/output),
//        1 = QK^T (batched z=48, transB),  2 = attn@V (batched z=48),
//        3 = plain output GEMM.
// ---------------------------------------------------------------------------
__global__ void __launch_bounds__(256, 2)
gemm_tc(const float* __restrict__ A0, const float* __restrict__ A1, const float* __restrict__ A2,
        const float* __restrict__ B0, const float* __restrict__ B1, const float* __restrict__ B2,
        const float* __restrict__ bi0, const float* __restrict__ bi1, const float* __restrict__ bi2,
        float* __restrict__ C0, float* __restrict__ C1, float* __restrict__ C2,
        int N, int K, long aBatch, long bBatch, int transB, int mode)
{
    __shared__ uint32_t As[2][128 * 20];
    __shared__ uint32_t Bs[2][16 * 72];
    int tid = threadIdx.x, lane = tid & 31, wid = tid >> 5;
    int z = blockIdx.z;

    const float *A, *B, *bias = nullptr;
    float* C;
    float scale = 1.f;
    long cOff = 0;
    int ldc = N;
    int headLayout = 0;

    if (mode == 0) {
        A = (z == 0) ? A0 : (z == 1) ? A1 : A2;
        B = (z == 0) ? B0 : (z == 1) ? B1 : B2;
        bias = (z == 0) ? bi0 : (z == 1) ? bi1 : bi2;
        C = (z == 0) ? C0 : (z == 1) ? C1 : C2;
        scale = (z == 0) ? 0.125f : 1.f;
        headLayout = 1;
    } else if (mode == 1) {
        A = A0 + (long)z * aBatch; B = B0 + (long)z * bBatch; C = C0;
        cOff = (long)z * Ssz * Ssz; ldc = Ssz;
    } else if (mode == 2) {
        A = A0 + (long)z * aBatch; B = B0 + (long)z * bBatch; C = C0;
        cOff = (long)(z / Hn) * Ssz * Dsz + (long)(z % Hn) * DHn; ldc = Dsz;
    } else {
        A = A0; B = B0; bias = bi0; C = C0;
    }

    const float* Ab = A + (long)blockIdx.y * 128 * K;
    int am = tid >> 2, akv = (tid & 3) * 4;   // A load: rows am, am+64; 4 k each
    int bkk = tid >> 4, bnv = (tid & 15) * 4; // B non-trans
    int bn = tid >> 2, bkv = (tid & 3) * 4;   // B trans

    auto ldA = [&](int k0, float4& r0, float4& r1) {
        const float* p = Ab + (long)am * K + k0 + akv;
        r0 = *(const float4*)p;
        r1 = *(const float4*)(p + (long)64 * K);
    };
    auto ldB = [&](int k0, float4& rb) {
        if (!transB) rb = *(const float4*)(B + (long)(k0 + bkk) * N + blockIdx.x * 64 + bnv);
        else         rb = *(const float4*)(B + (long)(blockIdx.x * 64 + bn) * K + k0 + bkv);
    };
    auto stA = [&](int buf, const float4& r0, const float4& r1) {
        #pragma unroll
        for (int j = 0; j < 4; j++) {
            As[buf][am * 20 + akv + j]        = f2tf(((const float*)&r0)[j]);
            As[buf][(am + 64) * 20 + akv + j] = f2tf(((const float*)&r1)[j]);
        }
    };
    auto stB = [&](int buf, const float4& rb) {
        if (!transB) {
            #pragma unroll
            for (int j = 0; j < 4; j++) Bs[buf][bkk * 72 + bnv + j] = f2tf(((const float*)&rb)[j]);
        } else {
            #pragma unroll
            for (int j = 0; j < 4; j++) Bs[buf][(bkv + j) * 72 + bn] = f2tf(((const float*)&rb)[j]);
        }
    };

    float acc[2][4][4] = {};
    int nt = K / 16;
    {
        float4 a0, a1, b0;
        ldA(0, a0, a1); ldB(0, b0);
        stA(0, a0, a1); stB(0, b0);
    }
    __syncthreads();

    int wm = (wid >> 1) * 32, wn = (wid & 1) * 32;
    int r = lane >> 2, tg = lane & 3;
    int cur = 0;
    for (int kt = 0; kt < nt; kt++) {
        float4 pa0, pa1, pb;
        bool pre = (kt + 1 < nt);
        if (pre) { ldA((kt + 1) * 16, pa0, pa1); ldB((kt + 1) * 16, pb); }
        const uint32_t* as = As[cur];
        const uint32_t* bs = Bs[cur];
        #pragma unroll
        for (int kc = 0; kc < 16; kc += 8) {
            uint32_t af[2][4], bf[4][2];
            #pragma unroll
            for (int mf = 0; mf < 2; mf++) {
                int rb_ = wm + mf * 16 + r;
                af[mf][0] = as[rb_ * 20 + kc + tg];
                af[mf][1] = as[(rb_ + 8) * 20 + kc + tg];
                af[mf][2] = as[rb_ * 20 + kc + tg + 4];
                af[mf][3] = as[(rb_ + 8) * 20 + kc + tg + 4];
            }
            #pragma unroll
            for (int nf = 0; nf < 4; nf++) {
                int nb = wn + nf * 8 + r;
                bf[nf][0] = bs[(kc + tg) * 72 + nb];
                bf[nf][1] = bs[(kc + tg + 4) * 72 + nb];
            }
            #pragma unroll
            for (int mf = 0; mf < 2; mf++)
                #pragma unroll
                for (int nf = 0; nf < 4; nf++)
                    mma8(acc[mf][nf][0], acc[mf][nf][1], acc[mf][nf][2], acc[mf][nf][3],
                         af[mf][0], af[mf][1], af[mf][2], af[mf][3],
                         bf[nf][0], bf[nf][1]);
        }
        if (pre) {
            int nxt = cur ^ 1;
            stA(nxt, pa0, pa1); stB(nxt, pb);
            __syncthreads();
            cur = nxt;
        }
    }

    #pragma unroll
    for (int mf = 0; mf < 2; mf++) {
        #pragma unroll
        for (int nf = 0; nf < 4; nf++) {
            int row0 = blockIdx.y * 128 + wm + mf * 16 + r;
            int col0 = blockIdx.x * 64 + wn + nf * 8 + 2 * tg;
            #pragma unroll
            for (int half = 0; half < 2; half++) {
                int m = row0 + half * 8;
                float v0 = acc[mf][nf][half * 2 + 0];
                float v1 = acc[mf][nf][half * 2 + 1];
                if (bias) { v0 += bias[col0]; v1 += bias[col0 + 1]; }
                v0 *= scale; v1 *= scale;
                long off;
                if (headLayout) {
                    int b = m >> 9, s = m & 511;
                    int h = col0 >> 6, d = col0 & 63;
                    off = (((long)b * Hn + h) * Ssz + s) * DHn + d;
                } else {
                    off = cOff + (long)m * ldc + col0;
                }
                float2 w = make_float2(v0, v1);
                *(float2*)&C[off] = w;
            }
        }
    }
}

// qs[b,h,q,s] = sum_d q[b,h,q,d] * Wsk[s,d]
__global__ void qs_kernel(const float* __restrict__ q, const float* __restrict__ Wsk,
                          float* __restrict__ qs)
{
    int tid = threadIdx.x;
    int rl = tid / 30, s = tid % 30;
    long r = (long)blockIdx.x * 8 + rl;
    const float* qr = q + r * 64;
    const float* w = Wsk + s * 64;
    float acc = 0.f;
    #pragma unroll
    for (int d = 0; d < 64; d++) acc += qr[d] * w[d];
    qs[r * 30 + s] = acc;
}

// ---------------------------------------------------------------------------
// Fused: scores += qs.structure; mask; softmax (all 12 heads of one (b,q)
// row); write attn (+top for h==0); A[h][s] = sum_k attn*structure.
// Structure row (512x30) is loaded to smem ONCE and reused for both passes.
// Dynamic smem: st 512*31 + scr 12*512 + qss 360 + msk 512 = 22888 floats.
// ---------------------------------------------------------------------------
__global__ void struct_softmax(const float* __restrict__ structure,
                               const float* __restrict__ qs,
                               const void* __restrict__ mask,
                               float* __restrict__ sc,
                               float* __restrict__ Aout,
                               float* __restrict__ top)
{
    extern __shared__ float sm[];
    float* st  = sm;                  // [512][31]
    float* scr = st + 512 * 31;       // [12][512]
    float* qss = scr + 12 * 512;      // [12][30]
    float* msk = qss + 360;           // [512]
    int tid = threadIdx.x, lane = tid & 31, wid = tid >> 5;
    int qrow = blockIdx.x, b = blockIdx.y;

    const float* sb = structure + ((long)(b * Ssz + qrow)) * Ssz * SDn;
    for (int idx = tid; idx < 512 * 30; idx += 256)
        st[(idx / 30) * 31 + idx % 30] = sb[idx];
    for (int idx = tid; idx < 360; idx += 256)
        qss[idx] = qs[(((long)(b * Hn + idx / 30)) * Ssz + qrow) * SDn + idx % 30];
    {
        long mbase = ((long)(b * Ssz + qrow)) * Ssz;
        for (int idx = tid; idx < 512; idx += 256) {
            int mv = g_maskmode ? (int)((const unsigned char*)mask)[mbase + idx]
                                : (((const int*)mask)[mbase + idx] != 0);
            msk[idx] = mv ? 1.f : 0.f;
        }
    }
    for (int o = tid; o < 6144; o += 256) {
        int h = o >> 9, k = o & 511;
        scr[o] = sc[(long)(b * Hn + h) * Ssz * Ssz + (long)qrow * Ssz + k];
    }
    __syncthreads();

    // scores += qs . structure ; mask
    for (int o = tid; o < 6144; o += 256) {
        int h = o >> 9, k = o & 511;
        if (msk[k] != 0.f) {
            scr[o] = -1e18f;
        } else {
            float acc = scr[o];
            const float* qr = qss + h * 30;
            const float* sr = st + k * 31;
            #pragma unroll
            for (int s = 0; s < 30; s++) acc += qr[s] * sr[s];
            scr[o] = acc;
        }
    }
    __syncthreads();

    // per-head softmax (warp w handles heads w, w+8)
    for (int h = wid; h < 12; h += 8) {
        float* row = scr + h * 512;
        float vals[16];
        float vmax = -3.0e38f;
        #pragma unroll
        for (int i = 0; i < 16; i++) { vals[i] = row[i * 32 + lane]; vmax = fmaxf(vmax, vals[i]); }
        #pragma unroll
        for (int o2 = 16; o2 > 0; o2 >>= 1) vmax = fmaxf(vmax, __shfl_xor_sync(~0u, vmax, o2));
        float ssum = 0.f;
        #pragma unroll
        for (int i = 0; i < 16; i++) { vals[i] = __expf(vals[i] - vmax); ssum += vals[i]; }
        #pragma unroll
        for (int o2 = 16; o2 > 0; o2 >>= 1) ssum += __shfl_xor_sync(~0u, ssum, o2);
        float inv = 1.f / ssum;
        #pragma unroll
        for (int i = 0; i < 16; i++) row[i * 32 + lane] = vals[i] * inv;
    }
    __syncthreads();

    // write attn (+ top for h==0)
    for (int o = tid; o < 6144; o += 256) {
        int h = o >> 9, k = o & 511;
        float v = scr[o];
        sc[(long)(b * Hn + h) * Ssz * Ssz + (long)qrow * Ssz + k] = v;
        if (h == 0) top[((long)(b * Ssz + qrow)) * Ssz + k] = v;
    }

    // A[h][s] = sum_k attn[h][k] * st[k][s]  (structure reused from smem)
    for (int p = tid; p < 360; p += 256) {
        int h = p / 30, s = p % 30;
        const float* row = scr + h * 512;
        const float* stc = st + s;
        float acc = 0.f;
        #pragma unroll 8
        for (int k = 0; k < 512; k++) acc += row[k] * stc[k * 31];
        Aout[(((long)(b * Hn + h)) * Ssz + qrow) * SDn + s] = acc;
    }
}

// ctx[b,s,h*64+d] += sum_s A[b,h,q,s]*Wsv[s,d] + bsv[d]
__global__ void add_sv(const float* __restrict__ A, const float* __restrict__ Wsv,
                       const float* __restrict__ bsv, float* __restrict__ ctx)
{
    int tid = threadIdx.x;
    long r = (long)blockIdx.x * 4 + (tid >> 6);
    int d = tid & 63;
    const float* ar = A + r * 30;
    float acc = bsv[d];
    #pragma unroll
    for (int s = 0; s < 30; s++) acc += ar[s] * Wsv[s * 64 + d];
    int b = (int)(r / (Hn * Ssz));
    int h = (int)((r / Ssz) % Hn);
    int qrow = (int)(r % Ssz);
    ctx[(((long)(b * Ssz + qrow)) * Dsz) + h * 64 + d] += acc;
}

extern "C" void kernel_launch(void* const* d_in, const int* in_sizes, int n_in,
                              void* d_out, int out_size)
{
    const float* key       = (const float*)d_in[0];
    const float* value     = (const float*)d_in[1];
    const float* query     = (const float*)d_in[2];
    const float* structure = (const float*)d_in[3];
    const void*  mask      = d_in[4];
    const float* Wq  = (const float*)d_in[5];
    const float* bq  = (const float*)d_in[6];
    const float* Wk  = (const float*)d_in[7];
    const float* bk  = (const float*)d_in[8];
    const float* Wv  = (const float*)d_in[9];
    const float* bv  = (const float*)d_in[10];
    const float* Wsk = (const float*)d_in[11];
    // d_in[12] = bsk : softmax-invariant (constant over k), dropped.
    const float* Wsv = (const float*)d_in[13];
    const float* bsv = (const float*)d_in[14];
    const float* Wo  = (const float*)d_in[15];
    const float* bo  = (const float*)d_in[16];
    float* out = (float*)d_out;
    float* out_top = out + (long)Bsz * Ssz * Dsz;

    float *q, *k, *v, *ctx, *qs, *Aacc, *sc;
    cudaGetSymbolAddress((void**)&q,    g_q);
    cudaGetSymbolAddress((void**)&k,    g_k);
    cudaGetSymbolAddress((void**)&v,    g_v);
    cudaGetSymbolAddress((void**)&ctx,  g_ctx);
    cudaGetSymbolAddress((void**)&qs,   g_qs);
    cudaGetSymbolAddress((void**)&Aacc, g_A);
    cudaGetSymbolAddress((void**)&sc,   g_sc);

    const int mask_elems = Bsz * Ssz * Ssz;
    const int SMEM_SS = (512 * 31 + 12 * 512 + 360 + 512) * 4;  // 91552 B
    cudaFuncSetAttribute(struct_softmax,
                         cudaFuncAttributeMaxDynamicSharedMemorySize, SMEM_SS);

    detect_mask<<<1, 256>>>((const unsigned int*)mask, mask_elems / 4);

    // fused QKV projections (mode 0): one launch, 576 CTAs
    gemm_tc<<<dim3(12, 16, 3), 256>>>(query, key, value,
                                      Wq, Wk, Wv,
                                      bq, bk, bv,
                                      q, k, v,
                                      768, 768, 0, 0, 0, 0);
    // qs = q @ Wsk^T
    qs_kernel<<<3072, 240>>>(q, Wsk, qs);
    // scores = q @ k^T (mode 1, batched z=48, transB)
    gemm_tc<<<dim3(8, 4, 48), 256>>>(q, nullptr, nullptr,
                                     k, nullptr, nullptr,
                                     nullptr, nullptr, nullptr,
                                     sc, nullptr, nullptr,
                                     512, 64, (long)Ssz * DHn, (long)Ssz * DHn, 1, 1);
    // fused: scores += qs.structure; mask; softmax; attn out; A = attn.structure
    struct_softmax<<<dim3(512, 4), 256, SMEM_SS>>>(structure, qs, mask, sc, Aacc, out_top);
    // ctx = attn @ v (mode 2, batched z=48)
    gemm_tc<<<dim3(1, 4, 48), 256>>>(sc, nullptr, nullptr,
                                     v, nullptr, nullptr,
                                     nullptr, nullptr, nullptr,
                                     ctx, nullptr, nullptr,
                                     64, 512, (long)Ssz * Ssz, (long)Ssz * DHn, 0, 2);
    // ctx += A @ Wsv + bsv
    add_sv<<<6144, 256>>>(Aacc, Wsv, bsv, ctx);
    // out = ctx @ Wo + bo (mode 3)
    gemm_tc<<<dim3(12, 16, 1), 256>>>(ctx, nullptr, nullptr,
                                      Wo, nullptr, nullptr,
                                      bo, nullptr, nullptr,
                                      out, nullptr, nullptr,
                                      768, 768, 0, 0, 0, 3);
}

// round 11
// speedup vs baseline: 2.4517x; 2.4517x over previous
#include <cuda_runtime.h>
#include <cstdint>

#define Bsz 4
#define Ssz 512
#define Dsz 768
#define Hn  12
#define DHn 64
#define SDn 30

// ---- scratch (static device globals; no runtime allocation) ----
__device__ float g_q  [Bsz*Hn*Ssz*DHn];          // (B,H,S,DH) scaled q
__device__ float g_k  [Bsz*Hn*Ssz*DHn];
__device__ float g_v  [Bsz*Hn*Ssz*DHn];
__device__ float g_ctx[Bsz*Ssz*Dsz];             // (B,S,H*DH)
__device__ float g_qs [Bsz*Hn*Ssz*SDn];          // q @ Wsk^T
__device__ float g_A  [Bsz*Hn*Ssz*SDn];          // attn . structure
__device__ float g_sc [(size_t)Bsz*Hn*Ssz*Ssz];  // scores / attn (in place)

__device__ __forceinline__ uint32_t f2tf(float x)
{
    uint32_t u;
    asm("cvt.rna.tf32.f32 %0, %1;" : "=r"(u) : "f"(x));
    return u;
}

__device__ __forceinline__ void mma8(float& d0, float& d1, float& d2, float& d3,
                                     uint32_t a0, uint32_t a1, uint32_t a2, uint32_t a3,
                                     uint32_t b0, uint32_t b1)
{
    asm volatile("mma.sync.aligned.m16n8k8.row.col.f32.tf32.tf32.f32 "
                 "{%0,%1,%2,%3}, {%4,%5,%6,%7}, {%8,%9}, {%0,%1,%2,%3};\n"
                 : "+f"(d0), "+f"(d1), "+f"(d2), "+f"(d3)
                 : "r"(a0), "r"(a1), "r"(a2), "r"(a3), "r"(b0), "r"(b1));
}

// ---------------------------------------------------------------------------
// tf32 tensor-core GEMM: CTA tile 128x64, BK=16, 256 threads (8 warps, each
// computing 32x32 via m16n8k8 fragments), double-buffered smem.
// modes: 0 = fused QKV projections, 1 = QK^T (z=48, transB), 2 = attn@V, 3 = plain.
// ---------------------------------------------------------------------------
__global__ void __launch_bounds__(256, 2)
gemm_tc(const float* __restrict__ A0, const float* __restrict__ A1, const float* __restrict__ A2,
        const float* __restrict__ B0, const float* __restrict__ B1, const float* __restrict__ B2,
        const float* __restrict__ bi0, const float* __restrict__ bi1, const float* __restrict__ bi2,
        float* __restrict__ C0, float* __restrict__ C1, float* __restrict__ C2,
        int N, int K, long aBatch, long bBatch, int transB, int mode)
{
    __shared__ uint32_t As[2][128 * 20];
    __shared__ uint32_t Bs[2][16 * 72];
    int tid = threadIdx.x, lane = tid & 31, wid = tid >> 5;
    int z = blockIdx.z;

    const float *A, *B, *bias = nullptr;
    float* C;
    float scale = 1.f;
    long cOff = 0;
    int ldc = N;
    int headLayout = 0;

    if (mode == 0) {
        A = (z == 0) ? A0 : (z == 1) ? A1 : A2;
        B = (z == 0) ? B0 : (z == 1) ? B1 : B2;
        bias = (z == 0) ? bi0 : (z == 1) ? bi1 : bi2;
        C = (z == 0) ? C0 : (z == 1) ? C1 : C2;
        scale = (z == 0) ? 0.125f : 1.f;
        headLayout = 1;
    } else if (mode == 1) {
        A = A0 + (long)z * aBatch; B = B0 + (long)z * bBatch; C = C0;
        cOff = (long)z * Ssz * Ssz; ldc = Ssz;
    } else if (mode == 2) {
        A = A0 + (long)z * aBatch; B = B0 + (long)z * bBatch; C = C0;
        cOff = (long)(z / Hn) * Ssz * Dsz + (long)(z % Hn) * DHn; ldc = Dsz;
    } else {
        A = A0; B = B0; bias = bi0; C = C0;
    }

    const float* Ab = A + (long)blockIdx.y * 128 * K;
    int am = tid >> 2, akv = (tid & 3) * 4;
    int bkk = tid >> 4, bnv = (tid & 15) * 4;
    int bn = tid >> 2, bkv = (tid & 3) * 4;

    auto ldA = [&](int k0, float4& r0, float4& r1) {
        const float* p = Ab + (long)am * K + k0 + akv;
        r0 = *(const float4*)p;
        r1 = *(const float4*)(p + (long)64 * K);
    };
    auto ldB = [&](int k0, float4& rb) {
        if (!transB) rb = *(const float4*)(B + (long)(k0 + bkk) * N + blockIdx.x * 64 + bnv);
        else         rb = *(const float4*)(B + (long)(blockIdx.x * 64 + bn) * K + k0 + bkv);
    };
    auto stA = [&](int buf, const float4& r0, const float4& r1) {
        #pragma unroll
        for (int j = 0; j < 4; j++) {
            As[buf][am * 20 + akv + j]        = f2tf(((const float*)&r0)[j]);
            As[buf][(am + 64) * 20 + akv + j] = f2tf(((const float*)&r1)[j]);
        }
    };
    auto stB = [&](int buf, const float4& rb) {
        if (!transB) {
            #pragma unroll
            for (int j = 0; j < 4; j++) Bs[buf][bkk * 72 + bnv + j] = f2tf(((const float*)&rb)[j]);
        } else {
            #pragma unroll
            for (int j = 0; j < 4; j++) Bs[buf][(bkv + j) * 72 + bn] = f2tf(((const float*)&rb)[j]);
        }
    };

    float acc[2][4][4] = {};
    int nt = K / 16;
    {
        float4 a0, a1, b0;
        ldA(0, a0, a1); ldB(0, b0);
        stA(0, a0, a1); stB(0, b0);
    }
    __syncthreads();

    int wm = (wid >> 1) * 32, wn = (wid & 1) * 32;
    int r = lane >> 2, tg = lane & 3;
    int cur = 0;
    for (int kt = 0; kt < nt; kt++) {
        float4 pa0, pa1, pb;
        bool pre = (kt + 1 < nt);
        if (pre) { ldA((kt + 1) * 16, pa0, pa1); ldB((kt + 1) * 16, pb); }
        const uint32_t* as = As[cur];
        const uint32_t* bs = Bs[cur];
        #pragma unroll
        for (int kc = 0; kc < 16; kc += 8) {
            uint32_t af[2][4], bf[4][2];
            #pragma unroll
            for (int mf = 0; mf < 2; mf++) {
                int rb_ = wm + mf * 16 + r;
                af[mf][0] = as[rb_ * 20 + kc + tg];
                af[mf][1] = as[(rb_ + 8) * 20 + kc + tg];
                af[mf][2] = as[rb_ * 20 + kc + tg + 4];
                af[mf][3] = as[(rb_ + 8) * 20 + kc + tg + 4];
            }
            #pragma unroll
            for (int nf = 0; nf < 4; nf++) {
                int nb = wn + nf * 8 + r;
                bf[nf][0] = bs[(kc + tg) * 72 + nb];
                bf[nf][1] = bs[(kc + tg + 4) * 72 + nb];
            }
            #pragma unroll
            for (int mf = 0; mf < 2; mf++)
                #pragma unroll
                for (int nf = 0; nf < 4; nf++)
                    mma8(acc[mf][nf][0], acc[mf][nf][1], acc[mf][nf][2], acc[mf][nf][3],
                         af[mf][0], af[mf][1], af[mf][2], af[mf][3],
                         bf[nf][0], bf[nf][1]);
        }
        if (pre) {
            int nxt = cur ^ 1;
            stA(nxt, pa0, pa1); stB(nxt, pb);
            __syncthreads();
            cur = nxt;
        }
    }

    #pragma unroll
    for (int mf = 0; mf < 2; mf++) {
        #pragma unroll
        for (int nf = 0; nf < 4; nf++) {
            int row0 = blockIdx.y * 128 + wm + mf * 16 + r;
            int col0 = blockIdx.x * 64 + wn + nf * 8 + 2 * tg;
            #pragma unroll
            for (int half = 0; half < 2; half++) {
                int m = row0 + half * 8;
                float v0 = acc[mf][nf][half * 2 + 0];
                float v1 = acc[mf][nf][half * 2 + 1];
                if (bias) { v0 += bias[col0]; v1 += bias[col0 + 1]; }
                v0 *= scale; v1 *= scale;
                long off;
                if (headLayout) {
                    int b = m >> 9, s = m & 511;
                    int h = col0 >> 6, d = col0 & 63;
                    off = (((long)b * Hn + h) * Ssz + s) * DHn + d;
                } else {
                    off = cOff + (long)m * ldc + col0;
                }
                float2 w = make_float2(v0, v1);
                *(float2*)&C[off] = w;
            }
        }
    }
}

// qs[b,h,q,s] = sum_d q[b,h,q,d] * Wsk[s,d]
__global__ void qs_kernel(const float* __restrict__ q, const float* __restrict__ Wsk,
                          float* __restrict__ qs)
{
    int tid = threadIdx.x;
    int rl = tid / 30, s = tid % 30;
    long r = (long)blockIdx.x * 8 + rl;
    const float* qr = q + r * 64;
    const float* w = Wsk + s * 64;
    float acc = 0.f;
    #pragma unroll
    for (int d = 0; d < 64; d++) acc += qr[d] * w[d];
    qs[r * 30 + s] = acc;
}

// ---------------------------------------------------------------------------
// Fused structure pass v2. One CTA per (b,q), 384 threads (12 warps).
// Phase 1: scores += qs.structure (structure streamed in 128-k tiles through
//          smem, thread keeps its st row in registers, reused over heads);
//          mask applied.
// Phase 2: softmax, warp-per-head. attn written to sc (+top h==0).
// Phase 3: A[h][s] = sum_k attn[h][k]*st[k][s]; warp-per-head, 30 register
//          accumulators, structure re-streamed (L2-hot), shuffle reduction.
// Static smem: st 128*31 + scr 12*512 + qss 12*32 = 41984 B.
// ---------------------------------------------------------------------------
__global__ void __launch_bounds__(384, 2)
struct_softmax(const float* __restrict__ structure,
               const float* __restrict__ qs,
               const int* __restrict__ mask,
               float* __restrict__ sc,
               float* __restrict__ Aout,
               float* __restrict__ top)
{
    __shared__ float st[128 * 31];
    __shared__ float scr[12 * 512];
    __shared__ float qss[12 * 32];
    int tid = threadIdx.x, lane = tid & 31, wid = tid >> 5;
    int qrow = blockIdx.x, b = blockIdx.y;
    long rowbase = ((long)(b * Ssz + qrow)) * Ssz;      // for mask / structure rows
    const float* strow = structure + rowbase * SDn;

    // loads
    for (int i = tid; i < 12 * 32; i += 384) {
        int h = i >> 5, s = i & 31;
        qss[i] = (s < 30) ? qs[(((long)(b * Hn + h)) * Ssz + qrow) * SDn + s] : 0.f;
    }
    for (int i = tid; i < 6144; i += 384) {
        int h = i >> 9, k = i & 511;
        scr[i] = sc[((long)(b * Hn + h)) * Ssz * Ssz + (long)qrow * Ssz + k];
    }
    __syncthreads();

    // ---- Phase 1: score accumulation + mask, 4 k-tiles of 128 ----
    int kl = tid & 127;          // k within tile
    int hg = tid >> 7;           // 0..2 -> heads hg*4 .. hg*4+3
    for (int t = 0; t < 4; t++) {
        const float4* src = (const float4*)(strow + (long)t * 128 * SDn);
        for (int i = tid; i < 960; i += 384) {
            float4 vv = src[i];
            int base = i * 4;
            #pragma unroll
            for (int j = 0; j < 4; j++) {
                int e = base + j, r0 = e / 30, c0 = e - r0 * 30;
                st[r0 * 31 + c0] = ((const float*)&vv)[j];
            }
        }
        __syncthreads();
        int k = t * 128 + kl;
        int mv = mask[rowbase + k];
        if (mv) {
            #pragma unroll
            for (int hh = 0; hh < 4; hh++) scr[(hg * 4 + hh) * 512 + k] = -1e18f;
        } else {
            float stv[32];
            #pragma unroll
            for (int s = 0; s < 30; s++) stv[s] = st[kl * 31 + s];
            stv[30] = 0.f; stv[31] = 0.f;
            #pragma unroll
            for (int hh = 0; hh < 4; hh++) {
                int h = hg * 4 + hh;
                float a0 = 0, a1 = 0, a2 = 0, a3 = 0;
                #pragma unroll
                for (int s = 0; s < 32; s += 4) {
                    float4 qv = *(const float4*)&qss[h * 32 + s];
                    a0 += qv.x * stv[s];     a1 += qv.y * stv[s + 1];
                    a2 += qv.z * stv[s + 2]; a3 += qv.w * stv[s + 3];
                }
                scr[h * 512 + k] += (a0 + a1) + (a2 + a3);
            }
        }
        __syncthreads();
    }

    // ---- Phase 2: softmax, warp wid handles head wid (12 warps = 12 heads) ----
    {
        float* row = scr + wid * 512;
        float vals[16];
        float vmax = -3.0e38f;
        #pragma unroll
        for (int i = 0; i < 16; i++) { vals[i] = row[i * 32 + lane]; vmax = fmaxf(vmax, vals[i]); }
        #pragma unroll
        for (int o = 16; o > 0; o >>= 1) vmax = fmaxf(vmax, __shfl_xor_sync(~0u, vmax, o));
        float ssum = 0.f;
        #pragma unroll
        for (int i = 0; i < 16; i++) { vals[i] = __expf(vals[i] - vmax); ssum += vals[i]; }
        #pragma unroll
        for (int o = 16; o > 0; o >>= 1) ssum += __shfl_xor_sync(~0u, ssum, o);
        float inv = 1.f / ssum;
        #pragma unroll
        for (int i = 0; i < 16; i++) row[i * 32 + lane] = vals[i] * inv;
    }
    __syncthreads();

    // write attn (+ top for h==0)
    for (int i = tid; i < 6144; i += 384) {
        int h = i >> 9, k = i & 511;
        float v = scr[i];
        sc[((long)(b * Hn + h)) * Ssz * Ssz + (long)qrow * Ssz + k] = v;
        if (h == 0) top[rowbase + k] = v;
    }

    // ---- Phase 3: A = attn . structure, warp-per-head ----
    float acc[30];
    #pragma unroll
    for (int s = 0; s < 30; s++) acc[s] = 0.f;
    for (int t = 0; t < 4; t++) {
        __syncthreads();
        const float4* src = (const float4*)(strow + (long)t * 128 * SDn);
        for (int i = tid; i < 960; i += 384) {
            float4 vv = src[i];
            int base = i * 4;
            #pragma unroll
            for (int j = 0; j < 4; j++) {
                int e = base + j, r0 = e / 30, c0 = e - r0 * 30;
                st[r0 * 31 + c0] = ((const float*)&vv)[j];
            }
        }
        __syncthreads();
        const float* arow = scr + wid * 512 + t * 128;
        #pragma unroll
        for (int j = 0; j < 4; j++) {
            int kk = lane + 32 * j;
            float av = arow[kk];
            const float* sr = st + kk * 31;
            #pragma unroll
            for (int s = 0; s < 30; s++) acc[s] += av * sr[s];
        }
    }
    float outv = 0.f;
    #pragma unroll
    for (int s = 0; s < 30; s++) {
        float v = acc[s];
        #pragma unroll
        for (int o = 16; o > 0; o >>= 1) v += __shfl_xor_sync(~0u, v, o);
        if (lane == s) outv = v;
    }
    if (lane < 30)
        Aout[(((long)(b * Hn + wid)) * Ssz + qrow) * SDn + lane] = outv;
}

// ctx[b,s,h*64+d] += sum_s A[b,h,q,s]*Wsv[s,d] + bsv[d]
__global__ void add_sv(const float* __restrict__ A, const float* __restrict__ Wsv,
                       const float* __restrict__ bsv, float* __restrict__ ctx)
{
    int tid = threadIdx.x;
    long r = (long)blockIdx.x * 4 + (tid >> 6);
    int d = tid & 63;
    const float* ar = A + r * 30;
    float acc = bsv[d];
    #pragma unroll
    for (int s = 0; s < 30; s++) acc += ar[s] * Wsv[s * 64 + d];
    int b = (int)(r / (Hn * Ssz));
    int h = (int)((r / Ssz) % Hn);
    int qrow = (int)(r % Ssz);
    ctx[(((long)(b * Ssz + qrow)) * Dsz) + h * 64 + d] += acc;
}

extern "C" void kernel_launch(void* const* d_in, const int* in_sizes, int n_in,
                              void* d_out, int out_size)
{
    const float* key       = (const float*)d_in[0];
    const float* value     = (const float*)d_in[1];
    const float* query     = (const float*)d_in[2];
    const float* structure = (const float*)d_in[3];
    const int*   mask      = (const int*)d_in[4];   // bool -> int32 per harness
    const float* Wq  = (const float*)d_in[5];
    const float* bq  = (const float*)d_in[6];
    const float* Wk  = (const float*)d_in[7];
    const float* bk  = (const float*)d_in[8];
    const float* Wv  = (const float*)d_in[9];
    const float* bv  = (const float*)d_in[10];
    const float* Wsk = (const float*)d_in[11];
    // d_in[12] = bsk : softmax-invariant (constant over k), dropped.
    const float* Wsv = (const float*)d_in[13];
    const float* bsv = (const float*)d_in[14];
    const float* Wo  = (const float*)d_in[15];
    const float* bo  = (const float*)d_in[16];
    float* out = (float*)d_out;
    float* out_top = out + (long)Bsz * Ssz * Dsz;

    float *q, *k, *v, *ctx, *qs, *Aacc, *sc;
    cudaGetSymbolAddress((void**)&q,    g_q);
    cudaGetSymbolAddress((void**)&k,    g_k);
    cudaGetSymbolAddress((void**)&v,    g_v);
    cudaGetSymbolAddress((void**)&ctx,  g_ctx);
    cudaGetSymbolAddress((void**)&qs,   g_qs);
    cudaGetSymbolAddress((void**)&Aacc, g_A);
    cudaGetSymbolAddress((void**)&sc,   g_sc);

    // fused QKV projections (mode 0)
    gemm_tc<<<dim3(12, 16, 3), 256>>>(query, key, value,
                                      Wq, Wk, Wv,
                                      bq, bk, bv,
                                      q, k, v,
                                      768, 768, 0, 0, 0, 0);
    // qs = q @ Wsk^T
    qs_kernel<<<3072, 240>>>(q, Wsk, qs);
    // scores = q @ k^T (mode 1, batched z=48, transB)
    gemm_tc<<<dim3(8, 4, 48), 256>>>(q, nullptr, nullptr,
                                     k, nullptr, nullptr,
                                     nullptr, nullptr, nullptr,
                                     sc, nullptr, nullptr,
                                     512, 64, (long)Ssz * DHn, (long)Ssz * DHn, 1, 1);
    // fused: scores += qs.structure; mask; softmax; attn out; A = attn.structure
    struct_softmax<<<dim3(512, 4), 384>>>(structure, qs, mask, sc, Aacc, out_top);
    // ctx = attn @ v (mode 2, batched z=48)
    gemm_tc<<<dim3(1, 4, 48), 256>>>(sc, nullptr, nullptr,
                                     v, nullptr, nullptr,
                                     nullptr, nullptr, nullptr,
                                     ctx, nullptr, nullptr,
                                     64, 512, (long)Ssz * Ssz, (long)Ssz * DHn, 0, 2);
    // ctx += A @ Wsv + bsv
    add_sv<<<6144, 256>>>(Aacc, Wsv, bsv, ctx);
    // out = ctx @ Wo + bo (mode 3)
    gemm_tc<<<dim3(12, 16, 1), 256>>>(ctx, nullptr, nullptr,
                                      Wo, nullptr, nullptr,
                                      bo, nullptr, nullptr,
                                      out, nullptr, nullptr,
                                      768, 768, 0, 0, 0, 3);
}